// round 1
// baseline (speedup 1.0000x reference)
#include <cuda_runtime.h>
#include <cstdint>

#define NN 60000
#define EE 480000
#define CC 256
#define RR 16
#define NBAS 8
#define XBW 4096   // 2 RGCNs * 8 bases * 256

// ---------------- scratch (module-load allocated, no cudaMalloc) ----------------
__device__ float g_x   [(size_t)NN*CC];
__device__ float g_xb  [(size_t)NN*XBW];     // per node: [b<8]=bases1 products, [b>=8]=bases3
__device__ float g_Bcat[(size_t)CC*XBW];     // packed bases as [C, 4096]
__device__ float g_h1  [(size_t)NN*CC];
__device__ float g_h2  [(size_t)NN*CC];
__device__ float g_h1b [(size_t)NN*CC];
__device__ float g_h2b [(size_t)NN*CC];
__device__ float g_agg1[(size_t)NN*CC];
__device__ float g_agg2[(size_t)NN*CC];
__device__ float g_m1  [(size_t)NN*128];
__device__ float g_m2  [(size_t)NN*64];
__device__ int   g_cnt1[NN*RR];
__device__ int   g_cnt3[NN*RR];

// ---------------- kernels ----------------

__global__ void k_zero() {
    int i = blockIdx.x * blockDim.x + threadIdx.x;
    int stride = gridDim.x * blockDim.x;
    const int nf = NN * CC;
    for (int j = i; j < nf; j += stride) {
        g_h1[j] = 0.f; g_h2[j] = 0.f; g_agg1[j] = 0.f; g_agg2[j] = 0.f;
    }
    const int nc = NN * RR;
    for (int j = i; j < nc; j += stride) { g_cnt1[j] = 0; g_cnt3[j] = 0; }
}

__global__ void k_x(const float* __restrict__ enc, const int* __restrict__ spk,
                    const float* __restrict__ table) {
    int i = blockIdx.x * blockDim.x + threadIdx.x;
    if (i >= NN * CC) return;
    int n = i >> 8, c = i & 255;
    g_x[i] = enc[i] + table[spk[n] * CC + c];
}

__global__ void k_hist(const int* __restrict__ dst, const int* __restrict__ et1,
                       const int* __restrict__ et3) {
    int e = blockIdx.x * blockDim.x + threadIdx.x;
    if (e >= EE) return;
    int d = dst[e];
    atomicAdd(&g_cnt1[d * RR + et1[e]], 1);
    atomicAdd(&g_cnt3[d * RR + et3[e]], 1);
}

// pack bases1/bases3 [8][256][256] -> g_Bcat [256][4096]
__global__ void k_pack(const float* __restrict__ bases1, const float* __restrict__ bases3) {
    int i = blockIdx.x * blockDim.x + threadIdx.x;
    if (i >= NBAS * CC * CC) return;
    int b = i / (CC * CC), rem = i % (CC * CC), c = rem / CC, o = rem % CC;
    g_Bcat[(size_t)c * XBW + b * CC + o]        = bases1[i];
    g_Bcat[(size_t)c * XBW + 2048 + b * CC + o] = bases3[i];
}

// per-edge RGCN message: out[dst] += norm * sum_b comp[rel,b] * xb[src,b,:]
__global__ void k_edge(const int* __restrict__ src, const int* __restrict__ dst,
                       const int* __restrict__ et, const float* __restrict__ comp,
                       const int* __restrict__ cnt, int xboff, float* __restrict__ out) {
    int e = blockIdx.x * (blockDim.x >> 5) + (threadIdx.x >> 5);
    int lane = threadIdx.x & 31;
    if (e >= EE) return;
    int s = src[e], d = dst[e], r = et[e];
    float cf[NBAS];
#pragma unroll
    for (int b = 0; b < NBAS; b++) cf[b] = comp[r * NBAS + b];
    float norm = 1.f / fmaxf((float)cnt[d * RR + r], 1.f);
    const float* xr = g_xb + (size_t)s * XBW + xboff;
    float* op = out + (size_t)d * CC;
#pragma unroll
    for (int k = 0; k < 2; k++) {
        int oo = lane * 4 + k * 128;
        float4 v = make_float4(0.f, 0.f, 0.f, 0.f);
#pragma unroll
        for (int b = 0; b < NBAS; b++) {
            float4 xv = *(const float4*)&xr[b * CC + oo];
            v.x += cf[b] * xv.x; v.y += cf[b] * xv.y;
            v.z += cf[b] * xv.z; v.w += cf[b] * xv.w;
        }
        atomicAdd(&op[oo + 0], norm * v.x);
        atomicAdd(&op[oo + 1], norm * v.y);
        atomicAdd(&op[oo + 2], norm * v.z);
        atomicAdd(&op[oo + 3], norm * v.w);
    }
}

// GraphConv aggregation: agg[dst] += h[src]
__global__ void k_scatter(const int* __restrict__ src, const int* __restrict__ dst,
                          const float* __restrict__ h, float* __restrict__ agg) {
    int e = blockIdx.x * (blockDim.x >> 5) + (threadIdx.x >> 5);
    int lane = threadIdx.x & 31;
    if (e >= EE) return;
    const float* hr = h + (size_t)src[e] * CC;
    float* ap = agg + (size_t)dst[e] * CC;
#pragma unroll
    for (int k = 0; k < 2; k++) {
        int oo = lane * 4 + k * 128;
        float4 v = *(const float4*)&hr[oo];
        atomicAdd(&ap[oo + 0], v.x);
        atomicAdd(&ap[oo + 1], v.y);
        atomicAdd(&ap[oo + 2], v.z);
        atomicAdd(&ap[oo + 3], v.w);
    }
}

// generic SGEMM: C = [acc?C] + A[M,K]@B[K,N] + [bias] ; optional relu
// A row-major lda, B row-major ldb, C row-major ldc. K % 8 == 0, N % 4 == 0.
__global__ __launch_bounds__(256) void sgemm(
    int M, int Nc, int K,
    const float* __restrict__ A, int lda,
    const float* __restrict__ B, int ldb,
    float* __restrict__ Cc, int ldc,
    const float* __restrict__ bias, int accflag, int reluflag)
{
    __shared__ float As[8][128];
    __shared__ float Bs[8][128];
    int tx = threadIdx.x;
    int row0 = blockIdx.y * 128, col0 = blockIdx.x * 128;
    int tr = (tx >> 4) << 3;
    int tc = (tx & 15) << 3;
    float acc[8][8];
#pragma unroll
    for (int i = 0; i < 8; i++)
#pragma unroll
        for (int j = 0; j < 8; j++) acc[i][j] = 0.f;

    int a_r = tx >> 1, a_c = (tx & 1) << 2;
    int b_r = tx >> 5, b_c = (tx & 31) << 2;

    for (int k0 = 0; k0 < K; k0 += 8) {
        float4 av = make_float4(0.f, 0.f, 0.f, 0.f);
        int gr = row0 + a_r;
        if (gr < M) av = *(const float4*)&A[(size_t)gr * lda + k0 + a_c];
        As[a_c + 0][a_r] = av.x;
        As[a_c + 1][a_r] = av.y;
        As[a_c + 2][a_r] = av.z;
        As[a_c + 3][a_r] = av.w;
        float4 bv = make_float4(0.f, 0.f, 0.f, 0.f);
        if (col0 + b_c < Nc) bv = *(const float4*)&B[(size_t)(k0 + b_r) * ldb + col0 + b_c];
        *(float4*)&Bs[b_r][b_c] = bv;
        __syncthreads();
#pragma unroll
        for (int kk = 0; kk < 8; kk++) {
            float ar[8], br[8];
            *(float4*)&ar[0] = *(const float4*)&As[kk][tr];
            *(float4*)&ar[4] = *(const float4*)&As[kk][tr + 4];
            *(float4*)&br[0] = *(const float4*)&Bs[kk][tc];
            *(float4*)&br[4] = *(const float4*)&Bs[kk][tc + 4];
#pragma unroll
            for (int i = 0; i < 8; i++)
#pragma unroll
                for (int j = 0; j < 8; j++) acc[i][j] += ar[i] * br[j];
        }
        __syncthreads();
    }
#pragma unroll
    for (int i = 0; i < 8; i++) {
        int r = row0 + tr + i;
        if (r >= M) break;
#pragma unroll
        for (int j = 0; j < 8; j++) {
            int cidx = col0 + tc + j;
            if (cidx >= Nc) break;
            float v = acc[i][j];
            size_t off = (size_t)r * ldc + cidx;
            if (accflag) v += Cc[off];
            if (bias) v += bias[cidx];
            if (reluflag) v = fmaxf(v, 0.f);
            Cc[off] = v;
        }
    }
}

// out[n] = dot(m2[n,:64], wd3) + bd3
__global__ void k_final(const float* __restrict__ wd3, const float* __restrict__ bd3,
                        float* __restrict__ out) {
    int n = blockIdx.x * (blockDim.x >> 5) + (threadIdx.x >> 5);
    int lane = threadIdx.x & 31;
    if (n >= NN) return;
    const float* m = g_m2 + (size_t)n * 64;
    float s = m[lane] * wd3[lane] + m[lane + 32] * wd3[lane + 32];
#pragma unroll
    for (int o = 16; o; o >>= 1) s += __shfl_xor_sync(0xffffffffu, s, o);
    if (lane == 0) out[n] = s + bd3[0];
}

// ---------------- host ----------------

static inline void gemm(int M, int Nc, int K, const float* A, int lda,
                        const float* B, int ldb, float* C, int ldc,
                        const float* bias, int acc, int relu) {
    dim3 g((Nc + 127) / 128, (M + 127) / 128);
    sgemm<<<g, 256>>>(M, Nc, K, A, lda, B, ldb, C, ldc, bias, acc, relu);
}

extern "C" void kernel_launch(void* const* d_in, const int* in_sizes, int n_in,
                              void* d_out, int out_size) {
    const float* enc      = (const float*)d_in[0];
    const int*   speaker  = (const int*)d_in[1];
    const int*   eidx     = (const int*)d_in[2];
    const int*   src      = eidx;
    const int*   dst      = eidx + EE;
    const int*   et       = (const int*)d_in[3];
    const int*   est      = (const int*)d_in[4];
    const float* spk_tab  = (const float*)d_in[5];
    const float* comp1    = (const float*)d_in[6];
    const float* bases1   = (const float*)d_in[7];
    const float* root1    = (const float*)d_in[8];
    const float* b1       = (const float*)d_in[9];
    const float* w2_rel   = (const float*)d_in[10];
    const float* b2       = (const float*)d_in[11];
    const float* w2_root  = (const float*)d_in[12];
    const float* comp3    = (const float*)d_in[13];
    const float* bases3   = (const float*)d_in[14];
    const float* root3    = (const float*)d_in[15];
    const float* b3       = (const float*)d_in[16];
    const float* w4_rel   = (const float*)d_in[17];
    const float* b4       = (const float*)d_in[18];
    const float* w4_root  = (const float*)d_in[19];
    const float* wd1      = (const float*)d_in[20];
    const float* bd1      = (const float*)d_in[21];
    const float* wd2      = (const float*)d_in[22];
    const float* bd2      = (const float*)d_in[23];
    const float* wd3      = (const float*)d_in[24];
    const float* bd3      = (const float*)d_in[25];
    float* out = (float*)d_out;

    float *px, *pxb, *pB, *ph1, *ph2, *ph1b, *ph2b, *pa1, *pa2, *pm1, *pm2;
    int *pc1, *pc3;
    cudaGetSymbolAddress((void**)&px,   g_x);
    cudaGetSymbolAddress((void**)&pxb,  g_xb);
    cudaGetSymbolAddress((void**)&pB,   g_Bcat);
    cudaGetSymbolAddress((void**)&ph1,  g_h1);
    cudaGetSymbolAddress((void**)&ph2,  g_h2);
    cudaGetSymbolAddress((void**)&ph1b, g_h1b);
    cudaGetSymbolAddress((void**)&ph2b, g_h2b);
    cudaGetSymbolAddress((void**)&pa1,  g_agg1);
    cudaGetSymbolAddress((void**)&pa2,  g_agg2);
    cudaGetSymbolAddress((void**)&pm1,  g_m1);
    cudaGetSymbolAddress((void**)&pm2,  g_m2);
    cudaGetSymbolAddress((void**)&pc1,  g_cnt1);
    cudaGetSymbolAddress((void**)&pc3,  g_cnt3);

    // 0) zero accumulators + counts
    k_zero<<<2048, 256>>>();
    // 1) x = encoding + spk_table[speaker]
    k_x<<<(NN * CC + 255) / 256, 256>>>(enc, speaker, spk_tab);
    // 2) per-(dst,rel) counts for both RGCNs
    k_hist<<<(EE + 255) / 256, 256>>>(dst, et, est);
    // 3) pack both basis sets -> [256, 4096]
    k_pack<<<(NBAS * CC * CC + 255) / 256, 256>>>(bases1, bases3);
    // 4) xb = x @ Bcat  (the big GEMM: 126 GFLOP)
    gemm(NN, XBW, CC, px, CC, pB, XBW, pxb, XBW, nullptr, 0, 0);

    // 5) RGCN1: edge combine + scatter, then root term
    k_edge<<<(EE + 7) / 8, 256>>>(src, dst, et, comp1, pc1, 0, ph1);
    gemm(NN, CC, CC, px, CC, root1, CC, ph1, CC, b1, 1, 0);
    // 6) GraphConv1
    k_scatter<<<(EE + 7) / 8, 256>>>(src, dst, ph1, pa1);
    gemm(NN, CC, CC, pa1, CC, w2_rel, CC, ph1b, CC, b2, 0, 0);
    gemm(NN, CC, CC, ph1, CC, w2_root, CC, ph1b, CC, nullptr, 1, 0);

    // 7) RGCN2 (speaker-type relations) + root
    k_edge<<<(EE + 7) / 8, 256>>>(src, dst, est, comp3, pc3, 2048, ph2);
    gemm(NN, CC, CC, px, CC, root3, CC, ph2, CC, b3, 1, 0);
    // 8) GraphConv2
    k_scatter<<<(EE + 7) / 8, 256>>>(src, dst, ph2, pa2);
    gemm(NN, CC, CC, pa2, CC, w4_rel, CC, ph2b, CC, b4, 0, 0);
    gemm(NN, CC, CC, ph2, CC, w4_root, CC, ph2b, CC, nullptr, 1, 0);

    // 9) MLP layer 1 fused over concat([enc, h1, h2]) without materializing feat
    gemm(NN, 128, CC, enc,  CC, wd1,             128, pm1, 128, bd1,     0, 0);
    gemm(NN, 128, CC, ph1b, CC, wd1 + 256 * 128, 128, pm1, 128, nullptr, 1, 0);
    gemm(NN, 128, CC, ph2b, CC, wd1 + 512 * 128, 128, pm1, 128, nullptr, 1, 1);
    // 10) MLP layer 2
    gemm(NN, 64, 128, pm1, 128, wd2, 64, pm2, 64, bd2, 0, 1);
    // 11) final dot -> out[N]
    k_final<<<(NN + 7) / 8, 256>>>(wd3, bd3, out);

    (void)in_sizes; (void)n_in; (void)out_size;
}

// round 5
// speedup vs baseline: 1.6193x; 1.6193x over previous
#include <cuda_runtime.h>
#include <cuda_bf16.h>
#include <cstdint>

#define NN 60000
#define EE 480000
#define CC 256
#define RR 16
#define XWW 8192   // 32 relations * 256

// ---------------- scratch (module-load allocated, no cudaMalloc) ----------------
__device__ float g_xw  [(size_t)NN*XWW];
__device__ float g_h1  [(size_t)NN*CC];
__device__ float g_h2  [(size_t)NN*CC];
__device__ float g_h1b [(size_t)NN*CC];
__device__ float g_h2b [(size_t)NN*CC];
__device__ float g_agg1[(size_t)NN*CC];
__device__ float g_agg2[(size_t)NN*CC];
__device__ float g_m1  [(size_t)NN*128];
__device__ float g_m2  [(size_t)NN*64];
__device__ int   g_cnt1[NN*RR];
__device__ int   g_cnt3[NN*RR];
__device__ __nv_bfloat16 g_ah [(size_t)NN*CC];   // A hi (reused per GEMM)
__device__ __nv_bfloat16 g_al [(size_t)NN*CC];   // A lo
__device__ __nv_bfloat16 g_wth[(size_t)XWW*CC];  // big W^T hi  [8192,256]
__device__ __nv_bfloat16 g_wtl[(size_t)XWW*CC];  // big W^T lo
__device__ __nv_bfloat16 g_bh [65536];           // small B^T hi (reused)
__device__ __nv_bfloat16 g_bl [65536];           // small B^T lo

// ---------------- helpers ----------------
__device__ __forceinline__ uint32_t smem_u32(const void* p) {
    uint32_t a;
    asm("{ .reg .u64 t; cvta.to.shared.u64 t, %1; cvt.u32.u64 %0, t; }" : "=r"(a) : "l"(p));
    return a;
}
__device__ __forceinline__ void ldx4(uint32_t addr, uint32_t& r0, uint32_t& r1,
                                     uint32_t& r2, uint32_t& r3) {
    asm volatile("ldmatrix.sync.aligned.m8n8.x4.shared.b16 {%0,%1,%2,%3}, [%4];"
                 : "=r"(r0), "=r"(r1), "=r"(r2), "=r"(r3) : "r"(addr));
}
__device__ __forceinline__ void mma16816(float* c, const uint32_t* a, const uint32_t* b) {
    asm volatile(
        "mma.sync.aligned.m16n8k16.row.col.f32.bf16.bf16.f32 "
        "{%0,%1,%2,%3}, {%4,%5,%6,%7}, {%8,%9}, {%0,%1,%2,%3};"
        : "+f"(c[0]), "+f"(c[1]), "+f"(c[2]), "+f"(c[3])
        : "r"(a[0]), "r"(a[1]), "r"(a[2]), "r"(a[3]), "r"(b[0]), "r"(b[1]));
}

// ---------------- small kernels ----------------
__global__ void k_zero() {
    int i = blockIdx.x * blockDim.x + threadIdx.x;
    int stride = gridDim.x * blockDim.x;
    const int nf = NN * CC;
    for (int j = i; j < nf; j += stride) {
        g_h1[j] = 0.f; g_h2[j] = 0.f; g_agg1[j] = 0.f; g_agg2[j] = 0.f;
    }
    const int nc = NN * RR;
    for (int j = i; j < nc; j += stride) { g_cnt1[j] = 0; g_cnt3[j] = 0; }
}

__global__ void k_hist(const int* __restrict__ dst, const int* __restrict__ et1,
                       const int* __restrict__ et3) {
    int e = blockIdx.x * blockDim.x + threadIdx.x;
    if (e >= EE) return;
    int d = dst[e];
    atomicAdd(&g_cnt1[d * RR + et1[e]], 1);
    atomicAdd(&g_cnt3[d * RR + et3[e]], 1);
}

// build W_cat^T bf16 hi/lo: row n=(r*256+o), col k=i ; W_r = sum_b comp[r,b]*bases[b]
__global__ void k_packW(const float* __restrict__ bases1, const float* __restrict__ comp1,
                        const float* __restrict__ bases3, const float* __restrict__ comp3) {
    int r = blockIdx.x;            // 0..31
    int i0 = blockIdx.y * 8;
    int o = threadIdx.x;           // 0..255
    const float* bases = (r < 16) ? bases1 : bases3;
    const float* comp  = (r < 16) ? comp1  : comp3;
    int rr = r & 15;
    float cf[8];
#pragma unroll
    for (int b = 0; b < 8; b++) cf[b] = comp[rr * 8 + b];
    for (int i = i0; i < i0 + 8; i++) {
        float acc = 0.f;
#pragma unroll
        for (int b = 0; b < 8; b++) acc += cf[b] * bases[b * 65536 + i * 256 + o];
        __nv_bfloat16 h = __float2bfloat16(acc);
        __nv_bfloat16 l = __float2bfloat16(acc - __bfloat162float(h));
        size_t oi = (size_t)(r * 256 + o) * CC + i;
        g_wth[oi] = h; g_wtl[oi] = l;
    }
}

__device__ __forceinline__ void split4(float4 v, uint2& ph, uint2& pl) {
    __nv_bfloat16 h0 = __float2bfloat16(v.x), h1 = __float2bfloat16(v.y);
    __nv_bfloat16 h2 = __float2bfloat16(v.z), h3 = __float2bfloat16(v.w);
    __nv_bfloat16 l0 = __float2bfloat16(v.x - __bfloat162float(h0));
    __nv_bfloat16 l1 = __float2bfloat16(v.y - __bfloat162float(h1));
    __nv_bfloat16 l2 = __float2bfloat16(v.z - __bfloat162float(h2));
    __nv_bfloat16 l3 = __float2bfloat16(v.w - __bfloat162float(h3));
    ph.x = (uint32_t)__bfloat16_as_ushort(h0) | ((uint32_t)__bfloat16_as_ushort(h1) << 16);
    ph.y = (uint32_t)__bfloat16_as_ushort(h2) | ((uint32_t)__bfloat16_as_ushort(h3) << 16);
    pl.x = (uint32_t)__bfloat16_as_ushort(l0) | ((uint32_t)__bfloat16_as_ushort(l1) << 16);
    pl.y = (uint32_t)__bfloat16_as_ushort(l2) | ((uint32_t)__bfloat16_as_ushort(l3) << 16);
}

// fp32 -> bf16 hi/lo
__global__ void k_cvtA(const float* __restrict__ in, int n4) {
    int i = blockIdx.x * blockDim.x + threadIdx.x;
    if (i >= n4) return;
    uint2 ph, pl;
    split4(((const float4*)in)[i], ph, pl);
    ((uint2*)g_ah)[i] = ph;
    ((uint2*)g_al)[i] = pl;
}

// x = enc + table[spk] -> bf16 hi/lo directly
__global__ void k_cvtX(const float* __restrict__ enc, const int* __restrict__ spk,
                       const float* __restrict__ table) {
    int i = blockIdx.x * blockDim.x + threadIdx.x;
    if (i >= NN * CC / 4) return;
    int n = i >> 6, c = i & 63;
    float4 e = ((const float4*)enc)[i];
    float4 t = ((const float4*)table)[spk[n] * 64 + c];
    e.x += t.x; e.y += t.y; e.z += t.z; e.w += t.w;
    uint2 ph, pl;
    split4(e, ph, pl);
    ((uint2*)g_ah)[i] = ph;
    ((uint2*)g_al)[i] = pl;
}

// fp32 weight [K,N] row-major -> B^T bf16 hi/lo [N,K]
__global__ void k_cvtB(const float* __restrict__ in, int K, int N) {
    int idx = blockIdx.x * blockDim.x + threadIdx.x;
    if (idx >= N * K) return;
    int n = idx / K, k = idx - n * K;
    float v = in[(size_t)k * N + n];
    __nv_bfloat16 h = __float2bfloat16(v);
    __nv_bfloat16 l = __float2bfloat16(v - __bfloat162float(h));
    g_bh[idx] = h; g_bl[idx] = l;
}

// RGCN edge: out[dst] += (1/cnt[dst,rel]) * xw[src, xwoff + rel*256 + :]
__global__ void k_edge(const int* __restrict__ src, const int* __restrict__ dst,
                       const int* __restrict__ et, const int* __restrict__ cnt,
                       int xwoff, float* __restrict__ out) {
    int e = blockIdx.x * (blockDim.x >> 5) + (threadIdx.x >> 5);
    int lane = threadIdx.x & 31;
    if (e >= EE) return;
    int s = src[e], d = dst[e], r = et[e];
    float norm = 1.f / fmaxf((float)cnt[d * RR + r], 1.f);
    const float4* xr = (const float4*)(g_xw + (size_t)s * XWW + xwoff + r * CC);
    float* op = out + (size_t)d * CC;
#pragma unroll
    for (int k = 0; k < 2; k++) {
        int o4 = lane + k * 32;
        float4 v = xr[o4];
        atomicAdd(&op[o4 * 4 + 0], norm * v.x);
        atomicAdd(&op[o4 * 4 + 1], norm * v.y);
        atomicAdd(&op[o4 * 4 + 2], norm * v.z);
        atomicAdd(&op[o4 * 4 + 3], norm * v.w);
    }
}

// GraphConv aggregation: agg[dst] += h[src]
__global__ void k_scatter(const int* __restrict__ src, const int* __restrict__ dst,
                          const float* __restrict__ h, float* __restrict__ agg) {
    int e = blockIdx.x * (blockDim.x >> 5) + (threadIdx.x >> 5);
    int lane = threadIdx.x & 31;
    if (e >= EE) return;
    const float4* hr = (const float4*)(h + (size_t)src[e] * CC);
    float* ap = agg + (size_t)dst[e] * CC;
#pragma unroll
    for (int k = 0; k < 2; k++) {
        int o4 = lane + k * 32;
        float4 v = hr[o4];
        atomicAdd(&ap[o4 * 4 + 0], v.x);
        atomicAdd(&ap[o4 * 4 + 1], v.y);
        atomicAdd(&ap[o4 * 4 + 2], v.z);
        atomicAdd(&ap[o4 * 4 + 3], v.w);
    }
}

// ---------------- HMMA GEMM (mma.sync bf16, hi/lo compensated) ----------------
// C[M,Nt] = (acc? C) + A[M,K] @ Bt[Nt,K]^T (+bias) (opt relu)
// CTA 128x128, 8 warps (2x4), warp tile 64x32, K-chunk 32.
// smem tiles [128][40] bf16 (80-byte pitch => conflict-free ldmatrix).
#define PITCH 40

__global__ __launch_bounds__(256) void hgemm(
    int M, int Nt, int K,
    const __nv_bfloat16* __restrict__ Ah, const __nv_bfloat16* __restrict__ Al,
    const __nv_bfloat16* __restrict__ Bh, const __nv_bfloat16* __restrict__ Bl,
    float* __restrict__ C, const float* __restrict__ bias, int accf, int reluf)
{
    __shared__ __align__(16) __nv_bfloat16 sAh[128 * PITCH];
    __shared__ __align__(16) __nv_bfloat16 sAl[128 * PITCH];
    __shared__ __align__(16) __nv_bfloat16 sBh[128 * PITCH];
    __shared__ __align__(16) __nv_bfloat16 sBl[128 * PITCH];

    int tid = threadIdx.x, wid = tid >> 5, lane = tid & 31;
    int m0 = blockIdx.y * 128, n0 = blockIdx.x * 128;
    int wm = (wid >> 2) * 64, wn = (wid & 3) * 32;

    float acc[4][4][4];
#pragma unroll
    for (int i = 0; i < 4; i++)
#pragma unroll
        for (int j = 0; j < 4; j++)
#pragma unroll
            for (int k = 0; k < 4; k++) acc[i][j][k] = 0.f;

    uint32_t uA0 = smem_u32(sAh), uA1 = smem_u32(sAl);
    uint32_t uB0 = smem_u32(sBh), uB1 = smem_u32(sBl);

    int nch = K >> 5;
    for (int ch = 0; ch < nch; ch++) {
        int k0 = ch << 5;
        // load 4 tiles: 128 rows x 32 cols each; 16B chunks, 8 per thread
#pragma unroll
        for (int i = 0; i < 8; i++) {
            const int tile = i >> 1;
            int w = ((i & 1) << 8) + tid;
            int row = w >> 2, c = w & 3;
            const __nv_bfloat16* g = tile == 0 ? Ah : tile == 1 ? Al : tile == 2 ? Bh : Bl;
            __nv_bfloat16* s = tile == 0 ? sAh : tile == 1 ? sAl : tile == 2 ? sBh : sBl;
            int rb = (tile < 2) ? m0 : n0;
            int rmax = (tile < 2) ? M : Nt;
            uint4 val = make_uint4(0, 0, 0, 0);
            if (rb + row < rmax)
                val = *(const uint4*)(g + (size_t)(rb + row) * K + k0 + c * 8);
            *(uint4*)(s + row * PITCH + c * 8) = val;
        }
        __syncthreads();

#pragma unroll
        for (int ks = 0; ks < 2; ks++) {
            int kb = ks * 32;  // byte offset of k16 step
            uint32_t bfr[2][4][2];
#pragma unroll
            for (int pair = 0; pair < 2; pair++) {
                int nrow = wn + pair * 16 + ((lane >> 4) & 1) * 8 + (lane & 7);
                int kbyte = kb + ((lane >> 3) & 1) * 16;
                uint32_t off = nrow * (PITCH * 2) + kbyte;
                ldx4(uB0 + off, bfr[0][pair * 2][0], bfr[0][pair * 2][1],
                     bfr[0][pair * 2 + 1][0], bfr[0][pair * 2 + 1][1]);
                ldx4(uB1 + off, bfr[1][pair * 2][0], bfr[1][pair * 2][1],
                     bfr[1][pair * 2 + 1][0], bfr[1][pair * 2 + 1][1]);
            }
#pragma unroll
            for (int mt = 0; mt < 4; mt++) {
                int arow = wm + mt * 16 + (lane & 15);
                int kbyte = kb + ((lane >> 4) & 1) * 16;
                uint32_t off = arow * (PITCH * 2) + kbyte;
                uint32_t ah[4], al[4];
                ldx4(uA0 + off, ah[0], ah[1], ah[2], ah[3]);
                ldx4(uA1 + off, al[0], al[1], al[2], al[3]);
#pragma unroll
                for (int nt = 0; nt < 4; nt++) {
                    mma16816(acc[mt][nt], ah, bfr[0][nt]);  // Ah*Bh
                    mma16816(acc[mt][nt], ah, bfr[1][nt]);  // Ah*Bl
                    mma16816(acc[mt][nt], al, bfr[0][nt]);  // Al*Bh
                }
            }
        }
        __syncthreads();
    }

    // epilogue
    int tr = lane >> 2, tc = (lane & 3) * 2;
#pragma unroll
    for (int mt = 0; mt < 4; mt++) {
#pragma unroll
        for (int nt = 0; nt < 4; nt++) {
            int c = n0 + wn + nt * 8 + tc;
            if (c >= Nt) continue;
#pragma unroll
            for (int half = 0; half < 2; half++) {
                int r = m0 + wm + mt * 16 + tr + half * 8;
                if (r >= M) continue;
                float v0 = acc[mt][nt][half * 2 + 0];
                float v1 = acc[mt][nt][half * 2 + 1];
                float* cp = C + (size_t)r * Nt + c;
                if (accf) { float2 o = *(const float2*)cp; v0 += o.x; v1 += o.y; }
                if (bias) { v0 += bias[c]; v1 += bias[c + 1]; }
                if (reluf) { v0 = fmaxf(v0, 0.f); v1 = fmaxf(v1, 0.f); }
                float2 w2 = make_float2(v0, v1);
                *(float2*)cp = w2;
            }
        }
    }
}

// out[n] = dot(m2[n,:64], wd3) + bd3
__global__ void k_final(const float* __restrict__ wd3, const float* __restrict__ bd3,
                        float* __restrict__ out) {
    int n = blockIdx.x * (blockDim.x >> 5) + (threadIdx.x >> 5);
    int lane = threadIdx.x & 31;
    if (n >= NN) return;
    const float* m = g_m2 + (size_t)n * 64;
    float s = m[lane] * wd3[lane] + m[lane + 32] * wd3[lane + 32];
#pragma unroll
    for (int o = 16; o; o >>= 1) s += __shfl_xor_sync(0xffffffffu, s, o);
    if (lane == 0) out[n] = s + bd3[0];
}

// ---------------- host ----------------
static void gemm(int M, int Nt, int K, const __nv_bfloat16* Ah, const __nv_bfloat16* Al,
                 const __nv_bfloat16* Bh, const __nv_bfloat16* Bl, float* C,
                 const float* bias, int acc, int relu) {
    dim3 g((Nt + 127) / 128, (M + 127) / 128);
    hgemm<<<g, 256>>>(M, Nt, K, Ah, Al, Bh, Bl, C, bias, acc, relu);
}

extern "C" void kernel_launch(void* const* d_in, const int* in_sizes, int n_in,
                              void* d_out, int out_size) {
    const float* enc     = (const float*)d_in[0];
    const int*   speaker = (const int*)d_in[1];
    const int*   eidx    = (const int*)d_in[2];
    const int*   src     = eidx;
    const int*   dst     = eidx + EE;
    const int*   et      = (const int*)d_in[3];
    const int*   est     = (const int*)d_in[4];
    const float* spk_tab = (const float*)d_in[5];
    const float* comp1   = (const float*)d_in[6];
    const float* bases1  = (const float*)d_in[7];
    const float* root1   = (const float*)d_in[8];
    const float* b1      = (const float*)d_in[9];
    const float* w2_rel  = (const float*)d_in[10];
    const float* b2      = (const float*)d_in[11];
    const float* w2_root = (const float*)d_in[12];
    const float* comp3   = (const float*)d_in[13];
    const float* bases3  = (const float*)d_in[14];
    const float* root3   = (const float*)d_in[15];
    const float* b3      = (const float*)d_in[16];
    const float* w4_rel  = (const float*)d_in[17];
    const float* b4      = (const float*)d_in[18];
    const float* w4_root = (const float*)d_in[19];
    const float* wd1     = (const float*)d_in[20];
    const float* bd1     = (const float*)d_in[21];
    const float* wd2     = (const float*)d_in[22];
    const float* bd2     = (const float*)d_in[23];
    const float* wd3     = (const float*)d_in[24];
    const float* bd3     = (const float*)d_in[25];
    float* out = (float*)d_out;

    float *pxw, *ph1, *ph2, *ph1b, *ph2b, *pa1, *pa2, *pm1, *pm2;
    int *pc1, *pc3;
    __nv_bfloat16 *pah, *pal, *pwh, *pwl, *pbh, *pbl;
    cudaGetSymbolAddress((void**)&pxw,  g_xw);
    cudaGetSymbolAddress((void**)&ph1,  g_h1);
    cudaGetSymbolAddress((void**)&ph2,  g_h2);
    cudaGetSymbolAddress((void**)&ph1b, g_h1b);
    cudaGetSymbolAddress((void**)&ph2b, g_h2b);
    cudaGetSymbolAddress((void**)&pa1,  g_agg1);
    cudaGetSymbolAddress((void**)&pa2,  g_agg2);
    cudaGetSymbolAddress((void**)&pm1,  g_m1);
    cudaGetSymbolAddress((void**)&pm2,  g_m2);
    cudaGetSymbolAddress((void**)&pc1,  g_cnt1);
    cudaGetSymbolAddress((void**)&pc3,  g_cnt3);
    cudaGetSymbolAddress((void**)&pah,  g_ah);
    cudaGetSymbolAddress((void**)&pal,  g_al);
    cudaGetSymbolAddress((void**)&pwh,  g_wth);
    cudaGetSymbolAddress((void**)&pwl,  g_wtl);
    cudaGetSymbolAddress((void**)&pbh,  g_bh);
    cudaGetSymbolAddress((void**)&pbl,  g_bl);

    const int NC4 = NN * CC / 4;

    k_zero<<<2048, 256>>>();
    k_hist<<<(EE + 255) / 256, 256>>>(dst, et, est);
    k_packW<<<dim3(32, 32), 256>>>(bases1, comp1, bases3, comp3);

    // x = enc + spk_table[speaker] -> hi/lo ; xw = x @ W_cat
    k_cvtX<<<(NC4 + 255) / 256, 256>>>(enc, speaker, spk_tab);
    gemm(NN, XWW, CC, pah, pal, pwh, pwl, pxw, nullptr, 0, 0);

    // RGCN edge aggregation (relation-direct)
    k_edge<<<(EE + 7) / 8, 256>>>(src, dst, et,  pc1, 0,    ph1);
    k_edge<<<(EE + 7) / 8, 256>>>(src, dst, est, pc3, 4096, ph2);

    // root terms (A = x, still resident in g_ah/g_al)
    k_cvtB<<<(CC * CC + 255) / 256, 256>>>(root1, CC, CC);
    gemm(NN, CC, CC, pah, pal, pbh, pbl, ph1, b1, 1, 0);
    k_cvtB<<<(CC * CC + 255) / 256, 256>>>(root3, CC, CC);
    gemm(NN, CC, CC, pah, pal, pbh, pbl, ph2, b3, 1, 0);

    // GraphConv aggregations
    k_scatter<<<(EE + 7) / 8, 256>>>(src, dst, ph1, pa1);
    k_scatter<<<(EE + 7) / 8, 256>>>(src, dst, ph2, pa2);

    // GraphConv1: h1b = h1@w2_root + (agg1@w2_rel + b2)
    k_cvtA<<<(NC4 + 255) / 256, 256>>>(ph1, NC4);
    k_cvtB<<<(CC * CC + 255) / 256, 256>>>(w2_root, CC, CC);
    gemm(NN, CC, CC, pah, pal, pbh, pbl, ph1b, nullptr, 0, 0);
    k_cvtA<<<(NC4 + 255) / 256, 256>>>(pa1, NC4);
    k_cvtB<<<(CC * CC + 255) / 256, 256>>>(w2_rel, CC, CC);
    gemm(NN, CC, CC, pah, pal, pbh, pbl, ph1b, b2, 1, 0);

    // GraphConv2
    k_cvtA<<<(NC4 + 255) / 256, 256>>>(ph2, NC4);
    k_cvtB<<<(CC * CC + 255) / 256, 256>>>(w4_root, CC, CC);
    gemm(NN, CC, CC, pah, pal, pbh, pbl, ph2b, nullptr, 0, 0);
    k_cvtA<<<(NC4 + 255) / 256, 256>>>(pa2, NC4);
    k_cvtB<<<(CC * CC + 255) / 256, 256>>>(w4_rel, CC, CC);
    gemm(NN, CC, CC, pah, pal, pbh, pbl, ph2b, b4, 1, 0);

    // MLP layer 1 fused over concat([enc, h1b, h2b])
    k_cvtA<<<(NC4 + 255) / 256, 256>>>(enc, NC4);
    k_cvtB<<<(CC * 128 + 255) / 256, 256>>>(wd1, CC, 128);
    gemm(NN, 128, CC, pah, pal, pbh, pbl, pm1, bd1, 0, 0);
    k_cvtA<<<(NC4 + 255) / 256, 256>>>(ph1b, NC4);
    k_cvtB<<<(CC * 128 + 255) / 256, 256>>>(wd1 + 256 * 128, CC, 128);
    gemm(NN, 128, CC, pah, pal, pbh, pbl, pm1, nullptr, 1, 0);
    k_cvtA<<<(NC4 + 255) / 256, 256>>>(ph2b, NC4);
    k_cvtB<<<(CC * 128 + 255) / 256, 256>>>(wd1 + 512 * 128, CC, 128);
    gemm(NN, 128, CC, pah, pal, pbh, pbl, pm1, nullptr, 1, 1);

    // MLP layer 2: m2 = relu(m1@wd2 + bd2)
    const int NM4 = NN * 128 / 4;
    k_cvtA<<<(NM4 + 255) / 256, 256>>>(pm1, NM4);
    k_cvtB<<<(128 * 64 + 255) / 256, 256>>>(wd2, 128, 64);
    gemm(NN, 64, 128, pah, pal, pbh, pbl, pm2, bd2, 0, 1);

    // final dot
    k_final<<<(NN + 7) / 8, 256>>>(wd3, bd3, out);

    (void)in_sizes; (void)n_in; (void)out_size;
}

// round 7
// speedup vs baseline: 2.2337x; 1.3795x over previous
#include <cuda_runtime.h>
#include <cuda_bf16.h>
#include <cstdint>

#define NN 60000
#define EE 480000
#define CC 256
#define RR 16
#define XWW 8192
#define NB1 (NN*RR)            // 960000 buckets per RGCN
#define AGGROWS 245760000      // 960000*256 floats per RGCN region
#define MAXT 7600

// ---------------- scratch (module-load allocated, no cudaMalloc) ----------------
__device__ float g_x   [(size_t)NN*CC];
__device__ float g_xw  [(size_t)NN*XWW];     // reused: compact agg rows (2 regions)
__device__ float g_h1  [(size_t)NN*CC];
__device__ float g_h2  [(size_t)NN*CC];
__device__ float g_h1b [(size_t)NN*CC];
__device__ float g_h2b [(size_t)NN*CC];
__device__ float g_agg1[(size_t)NN*CC];
__device__ float g_agg2[(size_t)NN*CC];
__device__ float g_m1  [(size_t)NN*128];
__device__ float g_m2  [(size_t)NN*64];
__device__ int   g_cnt1[NB1];
__device__ int   g_cnt3[NB1];
__device__ int   g_slot[2*NB1];
__device__ int   g_rowdst[2*NB1];
__device__ int   g_relcnt[32];
__device__ int   g_relfill[32];
__device__ int   g_tr[2*MAXT];
__device__ int   g_tb[2*MAXT];
__device__ int   g_tn[2*MAXT];
__device__ int   g_ntiles[2];
__device__ __nv_bfloat16 g_ah [(size_t)NN*CC];
__device__ __nv_bfloat16 g_al [(size_t)NN*CC];
__device__ __nv_bfloat16 g_wth[(size_t)XWW*CC];  // W^T hi [8192,256] (32 rel x 256)
__device__ __nv_bfloat16 g_wtl[(size_t)XWW*CC];
__device__ __nv_bfloat16 g_bh [65536];
__device__ __nv_bfloat16 g_bl [65536];

// ---------------- helpers ----------------
__device__ __forceinline__ uint32_t smem_u32(const void* p) {
    uint32_t a;
    asm("{ .reg .u64 t; cvta.to.shared.u64 t, %1; cvt.u32.u64 %0, t; }" : "=r"(a) : "l"(p));
    return a;
}
__device__ __forceinline__ void ldx4(uint32_t addr, uint32_t& r0, uint32_t& r1,
                                     uint32_t& r2, uint32_t& r3) {
    asm volatile("ldmatrix.sync.aligned.m8n8.x4.shared.b16 {%0,%1,%2,%3}, [%4];"
                 : "=r"(r0), "=r"(r1), "=r"(r2), "=r"(r3) : "r"(addr));
}
__device__ __forceinline__ void mma16816(float* c, const uint32_t* a, const uint32_t* b) {
    asm volatile(
        "mma.sync.aligned.m16n8k16.row.col.f32.bf16.bf16.f32 "
        "{%0,%1,%2,%3}, {%4,%5,%6,%7}, {%8,%9}, {%0,%1,%2,%3};"
        : "+f"(c[0]), "+f"(c[1]), "+f"(c[2]), "+f"(c[3])
        : "r"(a[0]), "r"(a[1]), "r"(a[2]), "r"(a[3]), "r"(b[0]), "r"(b[1]));
}
__device__ __forceinline__ void split4(float4 v, uint2& ph, uint2& pl) {
    __nv_bfloat16 h0 = __float2bfloat16(v.x), h1 = __float2bfloat16(v.y);
    __nv_bfloat16 h2 = __float2bfloat16(v.z), h3 = __float2bfloat16(v.w);
    __nv_bfloat16 l0 = __float2bfloat16(v.x - __bfloat162float(h0));
    __nv_bfloat16 l1 = __float2bfloat16(v.y - __bfloat162float(h1));
    __nv_bfloat16 l2 = __float2bfloat16(v.z - __bfloat162float(h2));
    __nv_bfloat16 l3 = __float2bfloat16(v.w - __bfloat162float(h3));
    ph.x = (uint32_t)__bfloat16_as_ushort(h0) | ((uint32_t)__bfloat16_as_ushort(h1) << 16);
    ph.y = (uint32_t)__bfloat16_as_ushort(h2) | ((uint32_t)__bfloat16_as_ushort(h3) << 16);
    pl.x = (uint32_t)__bfloat16_as_ushort(l0) | ((uint32_t)__bfloat16_as_ushort(l1) << 16);
    pl.y = (uint32_t)__bfloat16_as_ushort(l2) | ((uint32_t)__bfloat16_as_ushort(l3) << 16);
}

// ---------------- small kernels ----------------
__global__ void k_zero() {
    int i = blockIdx.x * blockDim.x + threadIdx.x;
    int stride = gridDim.x * blockDim.x;
    const int nf = NN * CC;
    for (int j = i; j < nf; j += stride) {
        g_h1[j] = 0.f; g_h2[j] = 0.f; g_agg1[j] = 0.f; g_agg2[j] = 0.f;
    }
    for (int j = i; j < NB1; j += stride) { g_cnt1[j] = 0; g_cnt3[j] = 0; }
    if (i < 32) { g_relcnt[i] = 0; g_relfill[i] = 0; }
}

__global__ void k_hist(const int* __restrict__ dst, const int* __restrict__ et1,
                       const int* __restrict__ et3) {
    int e = blockIdx.x * blockDim.x + threadIdx.x;
    if (e >= EE) return;
    int d = dst[e];
    atomicAdd(&g_cnt1[d * RR + et1[e]], 1);
    atomicAdd(&g_cnt3[d * RR + et3[e]], 1);
}

__global__ void k_nonempty() {
    int idx = blockIdx.x * blockDim.x + threadIdx.x;
    if (idx >= 2 * NB1) return;
    int q = idx / NB1, b = idx - q * NB1;
    int c = q ? g_cnt3[b] : g_cnt1[b];
    if (c > 0) atomicAdd(&g_relcnt[q * 16 + (b & 15)], 1);
}

__device__ int g_reloff[34];

// one block of 32 threads: thread i owns (q,r)=i; thread0 computes offsets serially
__global__ void k_buildtiles() {
    __shared__ int s_off[32], s_toff[32];
    int t = threadIdx.x;
    if (t == 0) {
        for (int q = 0; q < 2; q++) {
            int off = 0, toff = 0;
            for (int r = 0; r < 16; r++) {
                int i = q * 16 + r;
                s_off[i] = off; s_toff[i] = toff;
                int c = g_relcnt[i];
                g_reloff[q * 17 + r] = off;
                off += c;
                toff += (c + 127) >> 7;
            }
            g_reloff[q * 17 + 16] = off;
            g_ntiles[q] = toff;
        }
    }
    __syncthreads();
    int q = t >> 4, r = t & 15;
    int c = g_relcnt[t];
    int base = s_off[t], tile0 = s_toff[t];
    int nt = (c + 127) >> 7;
    for (int k = 0; k < nt; k++) {
        int idx = q * MAXT + tile0 + k;
        g_tr[idx] = r;
        g_tb[idx] = base + k * 128;
        g_tn[idx] = min(128, c - k * 128);
    }
}

// assign compact slots + zero agg rows
__global__ void k_slot() {
    int idx = blockIdx.x * blockDim.x + threadIdx.x;
    if (idx >= 2 * NB1) return;
    int q = idx / NB1, b = idx - q * NB1;
    int c = q ? g_cnt3[b] : g_cnt1[b];
    if (c <= 0) return;
    int r = b & 15;
    int s = g_reloff[q * 17 + r] + atomicAdd(&g_relfill[q * 16 + r], 1);
    g_slot[idx] = s;
    g_rowdst[q * NB1 + s] = b >> 4;
    float4* p = (float4*)(g_xw + (size_t)q * AGGROWS + (size_t)s * CC);
#pragma unroll
    for (int j = 0; j < 64; j++) p[j] = make_float4(0.f, 0.f, 0.f, 0.f);
}

// x = enc + table[spk]: write fp32 + bf16 hi/lo
__global__ void k_cvtX(const float* __restrict__ enc, const int* __restrict__ spk,
                       const float* __restrict__ table) {
    int i = blockIdx.x * blockDim.x + threadIdx.x;
    if (i >= NN * CC / 4) return;
    int n = i >> 6, c = i & 63;
    float4 e = ((const float4*)enc)[i];
    float4 t = ((const float4*)table)[spk[n] * 64 + c];
    e.x += t.x; e.y += t.y; e.z += t.z; e.w += t.w;
    ((float4*)g_x)[i] = e;
    uint2 ph, pl;
    split4(e, ph, pl);
    ((uint2*)g_ah)[i] = ph;
    ((uint2*)g_al)[i] = pl;
}

// build W_cat^T bf16 hi/lo
__global__ void k_packW(const float* __restrict__ bases1, const float* __restrict__ comp1,
                        const float* __restrict__ bases3, const float* __restrict__ comp3) {
    int r = blockIdx.x;
    int i0 = blockIdx.y * 8;
    int o = threadIdx.x;
    const float* bases = (r < 16) ? bases1 : bases3;
    const float* comp  = (r < 16) ? comp1  : comp3;
    int rr = r & 15;
    float cf[8];
#pragma unroll
    for (int b = 0; b < 8; b++) cf[b] = comp[rr * 8 + b];
    for (int i = i0; i < i0 + 8; i++) {
        float acc = 0.f;
#pragma unroll
        for (int b = 0; b < 8; b++) acc += cf[b] * bases[b * 65536 + i * 256 + o];
        __nv_bfloat16 h = __float2bfloat16(acc);
        __nv_bfloat16 l = __float2bfloat16(acc - __bfloat162float(h));
        size_t oi = (size_t)(r * 256 + o) * CC + i;
        g_wth[oi] = h; g_wtl[oi] = l;
    }
}

__global__ void k_cvtA(const float* __restrict__ in, int n4) {
    int i = blockIdx.x * blockDim.x + threadIdx.x;
    if (i >= n4) return;
    uint2 ph, pl;
    split4(((const float4*)in)[i], ph, pl);
    ((uint2*)g_ah)[i] = ph;
    ((uint2*)g_al)[i] = pl;
}

__global__ void k_cvtB(const float* __restrict__ in, int K, int N) {
    int idx = blockIdx.x * blockDim.x + threadIdx.x;
    if (idx >= N * K) return;
    int n = idx / K, k = idx - n * K;
    float v = in[(size_t)k * N + n];
    __nv_bfloat16 h = __float2bfloat16(v);
    __nv_bfloat16 l = __float2bfloat16(v - __bfloat162float(h));
    g_bh[idx] = h; g_bl[idx] = l;
}

// per-edge aggregation into compact buckets (both RGCNs; reads x once)
__global__ void k_edgeagg(const int* __restrict__ src, const int* __restrict__ dst,
                          const int* __restrict__ et, const int* __restrict__ est) {
    int e = blockIdx.x * (blockDim.x >> 5) + (threadIdx.x >> 5);
    int lane = threadIdx.x & 31;
    if (e >= EE) return;
    int s = src[e], d = dst[e];
    int b1 = d * RR + et[e], b3 = d * RR + est[e];
    int s1 = g_slot[b1], s3 = g_slot[NB1 + b3];
    float n1 = 1.f / (float)g_cnt1[b1];
    float n3 = 1.f / (float)g_cnt3[b3];
    const float4* xr = (const float4*)(g_x + (size_t)s * CC);
    float* a1 = g_xw + (size_t)s1 * CC;
    float* a3 = g_xw + (size_t)AGGROWS + (size_t)s3 * CC;
#pragma unroll
    for (int k = 0; k < 2; k++) {
        int o4 = lane + k * 32;
        float4 v = xr[o4];
        asm volatile("red.global.add.v4.f32 [%0], {%1,%2,%3,%4};"
                     :: "l"(a1 + o4 * 4), "f"(v.x * n1), "f"(v.y * n1),
                        "f"(v.z * n1), "f"(v.w * n1) : "memory");
        asm volatile("red.global.add.v4.f32 [%0], {%1,%2,%3,%4};"
                     :: "l"(a3 + o4 * 4), "f"(v.x * n3), "f"(v.y * n3),
                        "f"(v.z * n3), "f"(v.w * n3) : "memory");
    }
}

// GraphConv aggregation: agg[dst] += h[src]
__global__ void k_scatter(const int* __restrict__ src, const int* __restrict__ dst,
                          const float* __restrict__ h, float* __restrict__ agg) {
    int e = blockIdx.x * (blockDim.x >> 5) + (threadIdx.x >> 5);
    int lane = threadIdx.x & 31;
    if (e >= EE) return;
    const float4* hr = (const float4*)(h + (size_t)src[e] * CC);
    float* ap = agg + (size_t)dst[e] * CC;
#pragma unroll
    for (int k = 0; k < 2; k++) {
        int o4 = lane + k * 32;
        float4 v = hr[o4];
        asm volatile("red.global.add.v4.f32 [%0], {%1,%2,%3,%4};"
                     :: "l"(ap + o4 * 4), "f"(v.x), "f"(v.y), "f"(v.z), "f"(v.w) : "memory");
    }
}

#define PITCH 40

// ---------------- tile-list RGCN GEMM + scatter ----------------
// For tile t of RGCN q: rows = compact agg rows (fp32, converted in-flight),
// B = W_rel^T slice [128 x 256]; epilogue: h[dst] += result (atomic).
__global__ __launch_bounds__(256) void tcrgemm() {
    int q = blockIdx.z;
    if ((int)blockIdx.x >= g_ntiles[q]) return;
    int tid = threadIdx.x, wid = tid >> 5, lane = tid & 31;
    int ti = q * MAXT + blockIdx.x;
    int rel = g_tr[ti], mbase = g_tb[ti], mrows = g_tn[ti];
    const float* A = g_xw + (size_t)q * AGGROWS + (size_t)mbase * CC;
    const __nv_bfloat16* Bh = g_wth + ((size_t)(q * 16 + rel) * 256 + blockIdx.y * 128) * CC;
    const __nv_bfloat16* Bl = g_wtl + ((size_t)(q * 16 + rel) * 256 + blockIdx.y * 128) * CC;
    float* H = q ? g_h2 : g_h1;
    const int* rowdst = g_rowdst + q * NB1 + mbase;

    __shared__ __align__(16) __nv_bfloat16 sAh[128 * PITCH];
    __shared__ __align__(16) __nv_bfloat16 sAl[128 * PITCH];
    __shared__ __align__(16) __nv_bfloat16 sBh[128 * PITCH];
    __shared__ __align__(16) __nv_bfloat16 sBl[128 * PITCH];

    int wm = (wid >> 2) * 64, wn = (wid & 3) * 32;
    float acc[4][4][4];
#pragma unroll
    for (int i = 0; i < 4; i++)
#pragma unroll
        for (int j = 0; j < 4; j++)
#pragma unroll
            for (int k = 0; k < 4; k++) acc[i][j][k] = 0.f;

    uint32_t uA0 = smem_u32(sAh), uA1 = smem_u32(sAl);
    uint32_t uB0 = smem_u32(sBh), uB1 = smem_u32(sBl);

    int arow = tid >> 1, ahalf = tid & 1;
    bool avalid = arow < mrows;

    for (int ch = 0; ch < 8; ch++) {
        int k0 = ch << 5;
        // A: 128x32 fp32 -> bf16 hi/lo
        {
            const float4* ap = (const float4*)(A + (size_t)arow * CC + k0 + ahalf * 16);
#pragma unroll
            for (int j = 0; j < 4; j++) {
                float4 f = avalid ? ap[j] : make_float4(0.f, 0.f, 0.f, 0.f);
                uint2 ph, pl;
                split4(f, ph, pl);
                int off = arow * PITCH + ahalf * 16 + j * 4;
                *(uint2*)(sAh + off) = ph;
                *(uint2*)(sAl + off) = pl;
            }
        }
        // B tiles
#pragma unroll
        for (int i = 0; i < 4; i++) {
            const int tile = i >> 1;
            int w = ((i & 1) << 8) + tid;
            int row = w >> 2, c = w & 3;
            const __nv_bfloat16* g = tile == 0 ? Bh : Bl;
            __nv_bfloat16* sp = tile == 0 ? sBh : sBl;
            uint4 val = *(const uint4*)(g + (size_t)row * CC + k0 + c * 8);
            *(uint4*)(sp + row * PITCH + c * 8) = val;
        }
        __syncthreads();
#pragma unroll
        for (int ks = 0; ks < 2; ks++) {
            int kb = ks * 32;
            uint32_t bfr[2][4][2];
#pragma unroll
            for (int pair = 0; pair < 2; pair++) {
                int nrow = wn + pair * 16 + ((lane >> 4) & 1) * 8 + (lane & 7);
                int kbyte = kb + ((lane >> 3) & 1) * 16;
                uint32_t off = nrow * (PITCH * 2) + kbyte;
                ldx4(uB0 + off, bfr[0][pair * 2][0], bfr[0][pair * 2][1],
                     bfr[0][pair * 2 + 1][0], bfr[0][pair * 2 + 1][1]);
                ldx4(uB1 + off, bfr[1][pair * 2][0], bfr[1][pair * 2][1],
                     bfr[1][pair * 2 + 1][0], bfr[1][pair * 2 + 1][1]);
            }
#pragma unroll
            for (int mt = 0; mt < 4; mt++) {
                int ar = wm + mt * 16 + (lane & 15);
                int kbyte = kb + ((lane >> 4) & 1) * 16;
                uint32_t off = ar * (PITCH * 2) + kbyte;
                uint32_t ah[4], al[4];
                ldx4(uA0 + off, ah[0], ah[1], ah[2], ah[3]);
                ldx4(uA1 + off, al[0], al[1], al[2], al[3]);
#pragma unroll
                for (int nt = 0; nt < 4; nt++) {
                    mma16816(acc[mt][nt], ah, bfr[0][nt]);
                    mma16816(acc[mt][nt], ah, bfr[1][nt]);
                    mma16816(acc[mt][nt], al, bfr[0][nt]);
                }
            }
        }
        __syncthreads();
    }

    // epilogue: scatter rows to h[dst] with atomic adds
    int tr = lane >> 2, tc = (lane & 3) * 2;
    int col0 = blockIdx.y * 128;
#pragma unroll
    for (int mt = 0; mt < 4; mt++) {
#pragma unroll
        for (int half = 0; half < 2; half++) {
            int rl = wm + mt * 16 + tr + half * 8;
            if (rl >= mrows) continue;
            int d = rowdst[rl];
            float* hp = H + (size_t)d * CC + col0 + wn;
#pragma unroll
            for (int nt = 0; nt < 4; nt++) {
                float v0 = acc[mt][nt][half * 2 + 0];
                float v1 = acc[mt][nt][half * 2 + 1];
                asm volatile("red.global.add.v2.f32 [%0], {%1,%2};"
                             :: "l"(hp + nt * 8 + tc), "f"(v0), "f"(v1) : "memory");
            }
        }
    }
}

// ---------------- generic HMMA GEMM (unchanged core) ----------------
__global__ __launch_bounds__(256) void hgemm(
    int M, int Nt, int K,
    const __nv_bfloat16* __restrict__ Ah, const __nv_bfloat16* __restrict__ Al,
    const __nv_bfloat16* __restrict__ Bh, const __nv_bfloat16* __restrict__ Bl,
    float* __restrict__ C, const float* __restrict__ bias, int accf, int reluf)
{
    __shared__ __align__(16) __nv_bfloat16 sAh[128 * PITCH];
    __shared__ __align__(16) __nv_bfloat16 sAl[128 * PITCH];
    __shared__ __align__(16) __nv_bfloat16 sBh[128 * PITCH];
    __shared__ __align__(16) __nv_bfloat16 sBl[128 * PITCH];

    int tid = threadIdx.x, wid = tid >> 5, lane = tid & 31;
    int m0 = blockIdx.y * 128, n0 = blockIdx.x * 128;
    int wm = (wid >> 2) * 64, wn = (wid & 3) * 32;

    float acc[4][4][4];
#pragma unroll
    for (int i = 0; i < 4; i++)
#pragma unroll
        for (int j = 0; j < 4; j++)
#pragma unroll
            for (int k = 0; k < 4; k++) acc[i][j][k] = 0.f;

    uint32_t uA0 = smem_u32(sAh), uA1 = smem_u32(sAl);
    uint32_t uB0 = smem_u32(sBh), uB1 = smem_u32(sBl);

    int nch = K >> 5;
    for (int ch = 0; ch < nch; ch++) {
        int k0 = ch << 5;
#pragma unroll
        for (int i = 0; i < 8; i++) {
            const int tile = i >> 1;
            int w = ((i & 1) << 8) + tid;
            int row = w >> 2, c = w & 3;
            const __nv_bfloat16* g = tile == 0 ? Ah : tile == 1 ? Al : tile == 2 ? Bh : Bl;
            __nv_bfloat16* s = tile == 0 ? sAh : tile == 1 ? sAl : tile == 2 ? sBh : sBl;
            int rb = (tile < 2) ? m0 : n0;
            int rmax = (tile < 2) ? M : Nt;
            uint4 val = make_uint4(0, 0, 0, 0);
            if (rb + row < rmax)
                val = *(const uint4*)(g + (size_t)(rb + row) * K + k0 + c * 8);
            *(uint4*)(s + row * PITCH + c * 8) = val;
        }
        __syncthreads();
#pragma unroll
        for (int ks = 0; ks < 2; ks++) {
            int kb = ks * 32;
            uint32_t bfr[2][4][2];
#pragma unroll
            for (int pair = 0; pair < 2; pair++) {
                int nrow = wn + pair * 16 + ((lane >> 4) & 1) * 8 + (lane & 7);
                int kbyte = kb + ((lane >> 3) & 1) * 16;
                uint32_t off = nrow * (PITCH * 2) + kbyte;
                ldx4(uB0 + off, bfr[0][pair * 2][0], bfr[0][pair * 2][1],
                     bfr[0][pair * 2 + 1][0], bfr[0][pair * 2 + 1][1]);
                ldx4(uB1 + off, bfr[1][pair * 2][0], bfr[1][pair * 2][1],
                     bfr[1][pair * 2 + 1][0], bfr[1][pair * 2 + 1][1]);
            }
#pragma unroll
            for (int mt = 0; mt < 4; mt++) {
                int arow = wm + mt * 16 + (lane & 15);
                int kbyte = kb + ((lane >> 4) & 1) * 16;
                uint32_t off = arow * (PITCH * 2) + kbyte;
                uint32_t ah[4], al[4];
                ldx4(uA0 + off, ah[0], ah[1], ah[2], ah[3]);
                ldx4(uA1 + off, al[0], al[1], al[2], al[3]);
#pragma unroll
                for (int nt = 0; nt < 4; nt++) {
                    mma16816(acc[mt][nt], ah, bfr[0][nt]);
                    mma16816(acc[mt][nt], ah, bfr[1][nt]);
                    mma16816(acc[mt][nt], al, bfr[0][nt]);
                }
            }
        }
        __syncthreads();
    }

    int tr = lane >> 2, tc = (lane & 3) * 2;
#pragma unroll
    for (int mt = 0; mt < 4; mt++) {
#pragma unroll
        for (int nt = 0; nt < 4; nt++) {
            int c = n0 + wn + nt * 8 + tc;
            if (c >= Nt) continue;
#pragma unroll
            for (int half = 0; half < 2; half++) {
                int r = m0 + wm + mt * 16 + tr + half * 8;
                if (r >= M) continue;
                float v0 = acc[mt][nt][half * 2 + 0];
                float v1 = acc[mt][nt][half * 2 + 1];
                float* cp = C + (size_t)r * Nt + c;
                if (accf) { float2 o = *(const float2*)cp; v0 += o.x; v1 += o.y; }
                if (bias) { v0 += bias[c]; v1 += bias[c + 1]; }
                if (reluf) { v0 = fmaxf(v0, 0.f); v1 = fmaxf(v1, 0.f); }
                float2 w2 = make_float2(v0, v1);
                *(float2*)cp = w2;
            }
        }
    }
}

__global__ void k_final(const float* __restrict__ wd3, const float* __restrict__ bd3,
                        float* __restrict__ out) {
    int n = blockIdx.x * (blockDim.x >> 5) + (threadIdx.x >> 5);
    int lane = threadIdx.x & 31;
    if (n >= NN) return;
    const float* m = g_m2 + (size_t)n * 64;
    float s = m[lane] * wd3[lane] + m[lane + 32] * wd3[lane + 32];
#pragma unroll
    for (int o = 16; o; o >>= 1) s += __shfl_xor_sync(0xffffffffu, s, o);
    if (lane == 0) out[n] = s + bd3[0];
}

// ---------------- host ----------------
static void gemm(int M, int Nt, int K, const __nv_bfloat16* Ah, const __nv_bfloat16* Al,
                 const __nv_bfloat16* Bh, const __nv_bfloat16* Bl, float* C,
                 const float* bias, int acc, int relu) {
    dim3 g((Nt + 127) / 128, (M + 127) / 128);
    hgemm<<<g, 256>>>(M, Nt, K, Ah, Al, Bh, Bl, C, bias, acc, relu);
}

extern "C" void kernel_launch(void* const* d_in, const int* in_sizes, int n_in,
                              void* d_out, int out_size) {
    const float* enc     = (const float*)d_in[0];
    const int*   speaker = (const int*)d_in[1];
    const int*   eidx    = (const int*)d_in[2];
    const int*   src     = eidx;
    const int*   dst     = eidx + EE;
    const int*   et      = (const int*)d_in[3];
    const int*   est     = (const int*)d_in[4];
    const float* spk_tab = (const float*)d_in[5];
    const float* comp1   = (const float*)d_in[6];
    const float* bases1  = (const float*)d_in[7];
    const float* root1   = (const float*)d_in[8];
    const float* b1      = (const float*)d_in[9];
    const float* w2_rel  = (const float*)d_in[10];
    const float* b2      = (const float*)d_in[11];
    const float* w2_root = (const float*)d_in[12];
    const float* comp3   = (const float*)d_in[13];
    const float* bases3  = (const float*)d_in[14];
    const float* root3   = (const float*)d_in[15];
    const float* b3      = (const float*)d_in[16];
    const float* w4_rel  = (const float*)d_in[17];
    const float* b4      = (const float*)d_in[18];
    const float* w4_root = (const float*)d_in[19];
    const float* wd1     = (const float*)d_in[20];
    const float* bd1     = (const float*)d_in[21];
    const float* wd2     = (const float*)d_in[22];
    const float* bd2     = (const float*)d_in[23];
    const float* wd3     = (const float*)d_in[24];
    const float* bd3     = (const float*)d_in[25];
    float* out = (float*)d_out;

    float *ph1, *ph2, *ph1b, *ph2b, *pa1, *pa2, *pm1, *pm2;
    __nv_bfloat16 *pah, *pal, *pbh, *pbl;
    cudaGetSymbolAddress((void**)&ph1,  g_h1);
    cudaGetSymbolAddress((void**)&ph2,  g_h2);
    cudaGetSymbolAddress((void**)&ph1b, g_h1b);
    cudaGetSymbolAddress((void**)&ph2b, g_h2b);
    cudaGetSymbolAddress((void**)&pa1,  g_agg1);
    cudaGetSymbolAddress((void**)&pa2,  g_agg2);
    cudaGetSymbolAddress((void**)&pm1,  g_m1);
    cudaGetSymbolAddress((void**)&pm2,  g_m2);
    cudaGetSymbolAddress((void**)&pah,  g_ah);
    cudaGetSymbolAddress((void**)&pal,  g_al);
    cudaGetSymbolAddress((void**)&pbh,  g_bh);
    cudaGetSymbolAddress((void**)&pbl,  g_bl);

    const int NC4 = NN * CC / 4;

    k_zero<<<2048, 256>>>();
    k_cvtX<<<(NC4 + 255) / 256, 256>>>(enc, speaker, spk_tab);
    k_hist<<<(EE + 255) / 256, 256>>>(dst, et, est);
    k_packW<<<dim3(32, 32), 256>>>(bases1, comp1, bases3, comp3);

    // bucket compaction
    k_nonempty<<<(2 * NB1 + 255) / 256, 256>>>();
    k_buildtiles<<<1, 32>>>();
    k_slot<<<(2 * NB1 + 255) / 256, 256>>>();

    // per-edge fp32 aggregation into compact buckets (both RGCNs)
    k_edgeagg<<<(EE + 7) / 8, 256>>>(src, dst, et, est);

    // compacted RGCN GEMMs + scatter into h1/h2
    tcrgemm<<<dim3(MAXT, 2, 2), 256>>>();

    // root terms (A = x hi/lo, still resident)
    k_cvtB<<<(CC * CC + 255) / 256, 256>>>(root1, CC, CC);
    gemm(NN, CC, CC, pah, pal, pbh, pbl, ph1, b1, 1, 0);
    k_cvtB<<<(CC * CC + 255) / 256, 256>>>(root3, CC, CC);
    gemm(NN, CC, CC, pah, pal, pbh, pbl, ph2, b3, 1, 0);

    // GraphConv aggregations
    k_scatter<<<(EE + 7) / 8, 256>>>(src, dst, ph1, pa1);
    k_scatter<<<(EE + 7) / 8, 256>>>(src, dst, ph2, pa2);

    // GraphConv1
    k_cvtA<<<(NC4 + 255) / 256, 256>>>(ph1, NC4);
    k_cvtB<<<(CC * CC + 255) / 256, 256>>>(w2_root, CC, CC);
    gemm(NN, CC, CC, pah, pal, pbh, pbl, ph1b, nullptr, 0, 0);
    k_cvtA<<<(NC4 + 255) / 256, 256>>>(pa1, NC4);
    k_cvtB<<<(CC * CC + 255) / 256, 256>>>(w2_rel, CC, CC);
    gemm(NN, CC, CC, pah, pal, pbh, pbl, ph1b, b2, 1, 0);

    // GraphConv2
    k_cvtA<<<(NC4 + 255) / 256, 256>>>(ph2, NC4);
    k_cvtB<<<(CC * CC + 255) / 256, 256>>>(w4_root, CC, CC);
    gemm(NN, CC, CC, pah, pal, pbh, pbl, ph2b, nullptr, 0, 0);
    k_cvtA<<<(NC4 + 255) / 256, 256>>>(pa2, NC4);
    k_cvtB<<<(CC * CC + 255) / 256, 256>>>(w4_rel, CC, CC);
    gemm(NN, CC, CC, pah, pal, pbh, pbl, ph2b, b4, 1, 0);

    // MLP layer 1 fused over concat([enc, h1b, h2b])
    k_cvtA<<<(NC4 + 255) / 256, 256>>>(enc, NC4);
    k_cvtB<<<(CC * 128 + 255) / 256, 256>>>(wd1, CC, 128);
    gemm(NN, 128, CC, pah, pal, pbh, pbl, pm1, bd1, 0, 0);
    k_cvtA<<<(NC4 + 255) / 256, 256>>>(ph1b, NC4);
    k_cvtB<<<(CC * 128 + 255) / 256, 256>>>(wd1 + 256 * 128, CC, 128);
    gemm(NN, 128, CC, pah, pal, pbh, pbl, pm1, nullptr, 1, 0);
    k_cvtA<<<(NC4 + 255) / 256, 256>>>(ph2b, NC4);
    k_cvtB<<<(CC * 128 + 255) / 256, 256>>>(wd1 + 512 * 128, CC, 128);
    gemm(NN, 128, CC, pah, pal, pbh, pbl, pm1, nullptr, 1, 1);

    // MLP layer 2
    const int NM4 = NN * 128 / 4;
    k_cvtA<<<(NM4 + 255) / 256, 256>>>(pm1, NM4);
    k_cvtB<<<(128 * 64 + 255) / 256, 256>>>(wd2, 128, 64);
    gemm(NN, 64, 128, pah, pal, pbh, pbl, pm2, bd2, 0, 1);

    k_final<<<(NN + 7) / 8, 256>>>(wd3, bd3, out);

    (void)in_sizes; (void)n_in; (void)out_size;
}